// round 1
// baseline (speedup 1.0000x reference)
#include <cuda_runtime.h>

#define BATCH 262144
#define DIM   128
#define K     10

// Scratch for column sums of q (graph-capturable, no allocs).
__device__ float g_colsum[K];

typedef unsigned long long u64;

__device__ __forceinline__ u64 pack2(float lo, float hi) {
    u64 r; asm("mov.b64 %0, {%1, %2};" : "=l"(r) : "f"(lo), "f"(hi)); return r;
}
__device__ __forceinline__ void unpack2(u64 v, float& lo, float& hi) {
    asm("mov.b64 {%0, %1}, %2;" : "=f"(lo), "=f"(hi) : "l"(v));
}
__device__ __forceinline__ void fma2(u64& acc, u64 a, u64 b) {
    asm("fma.rn.f32x2 %0, %1, %2, %0;" : "+l"(acc) : "l"(a), "l"(b));
}

__global__ void k_zero() {
    if (threadIdx.x < K) g_colsum[threadIdx.x] = 0.0f;
}

// Kernel 1: q = rownorm( 1/(1+||z-c||^2) ), plus column sums of q.
// 2 rows per thread, 256 threads/block -> 512 rows/block, 512 blocks.
__global__ __launch_bounds__(256) void k_q(
    const float* __restrict__ z,
    const float* __restrict__ c,
    float* __restrict__ qout)
{
    __shared__ float4 s_c[K][DIM / 4];   // centers, 5120 B
    __shared__ float  s_cn[K];           // ||c_j||^2
    __shared__ float  s_part[8][K];      // per-warp column partials

    const int tid  = threadIdx.x;
    const int lane = tid & 31;
    const int wrp  = tid >> 5;

    // Cooperative load of centers (contiguous layout matches [K][DIM]).
    for (int i = tid; i < K * DIM / 4; i += 256)
        ((float4*)s_c)[i] = ((const float4*)c)[i];
    __syncthreads();
    if (tid < K) {
        float s = 0.0f;
        const float* cp = (const float*)s_c + tid * DIM;
        #pragma unroll 8
        for (int d = 0; d < DIM; d++) { float v = cp[d]; s = fmaf(v, v, s); }
        s_cn[tid] = s;
    }
    __syncthreads();

    const int row0 = blockIdx.x * 512 + tid;
    const int row1 = row0 + 256;

    const float4* z0 = (const float4*)(z + (size_t)row0 * DIM);
    const float4* z1 = (const float4*)(z + (size_t)row1 * DIM);

    u64 dot0[K], dot1[K];
    #pragma unroll
    for (int j = 0; j < K; j++) { dot0[j] = 0ull; dot1[j] = 0ull; }
    u64 zn0 = 0ull, zn1 = 0ull;

    #pragma unroll 8
    for (int s = 0; s < DIM / 4; s++) {
        float4 a = z0[s];
        float4 b = z1[s];
        u64 a01 = pack2(a.x, a.y), a23 = pack2(a.z, a.w);
        u64 b01 = pack2(b.x, b.y), b23 = pack2(b.z, b.w);
        fma2(zn0, a01, a01); fma2(zn0, a23, a23);
        fma2(zn1, b01, b01); fma2(zn1, b23, b23);
        #pragma unroll
        for (int j = 0; j < K; j++) {
            float4 cc = s_c[j][s];
            u64 c01 = pack2(cc.x, cc.y), c23 = pack2(cc.z, cc.w);
            fma2(dot0[j], a01, c01); fma2(dot0[j], a23, c23);
            fma2(dot1[j], b01, c01); fma2(dot1[j], b23, c23);
        }
    }

    float lo, hi;
    unpack2(zn0, lo, hi); const float zz0 = lo + hi;
    unpack2(zn1, lo, hi); const float zz1 = lo + hi;

    float q0[K], q1[K];
    float sum0 = 0.0f, sum1 = 0.0f;
    #pragma unroll
    for (int j = 0; j < K; j++) {
        unpack2(dot0[j], lo, hi); float d0 = lo + hi;
        unpack2(dot1[j], lo, hi); float d1 = lo + hi;
        float sq0 = zz0 - 2.0f * d0 + s_cn[j];
        float sq1 = zz1 - 2.0f * d1 + s_cn[j];
        float v0 = __fdividef(1.0f, 1.0f + sq0);
        float v1 = __fdividef(1.0f, 1.0f + sq1);
        q0[j] = v0; q1[j] = v1;
        sum0 += v0; sum1 += v1;
    }
    const float inv0 = __fdividef(1.0f, sum0);
    const float inv1 = __fdividef(1.0f, sum1);

    float* o0 = qout + (size_t)row0 * K;
    float* o1 = qout + (size_t)row1 * K;
    #pragma unroll
    for (int j = 0; j < K; j++) {
        q0[j] *= inv0; q1[j] *= inv1;
        o0[j] = q0[j];
        o1[j] = q1[j];
    }

    // Column sums: warp shuffle reduce, then block partials, then 10 atomics.
    #pragma unroll
    for (int j = 0; j < K; j++) {
        float v = q0[j] + q1[j];
        #pragma unroll
        for (int s = 16; s > 0; s >>= 1)
            v += __shfl_down_sync(0xFFFFFFFFu, v, s);
        if (lane == 0) s_part[wrp][j] = v;
    }
    __syncthreads();
    if (tid < K) {
        float s = 0.0f;
        #pragma unroll
        for (int w = 0; w < 8; w++) s += s_part[w][tid];
        atomicAdd(&g_colsum[tid], s);
    }
}

// Kernel 2: p = rownorm( q^2 / colsum )
__global__ __launch_bounds__(256) void k_p(
    const float* __restrict__ q,
    float* __restrict__ p)
{
    __shared__ float s_invf[K];
    if (threadIdx.x < K)
        s_invf[threadIdx.x] = __fdividef(1.0f, g_colsum[threadIdx.x]);
    __syncthreads();

    const int row = blockIdx.x * 256 + threadIdx.x;
    const float2* qr = (const float2*)(q + (size_t)row * K);
    float2* pr = (float2*)(p + (size_t)row * K);

    float w[K];
    float s = 0.0f;
    #pragma unroll
    for (int m = 0; m < K / 2; m++) {
        float2 v = qr[m];
        float w0 = v.x * v.x * s_invf[2 * m];
        float w1 = v.y * v.y * s_invf[2 * m + 1];
        w[2 * m] = w0; w[2 * m + 1] = w1;
        s += w0 + w1;
    }
    const float inv = __fdividef(1.0f, s);
    #pragma unroll
    for (int m = 0; m < K / 2; m++) {
        float2 v;
        v.x = w[2 * m] * inv;
        v.y = w[2 * m + 1] * inv;
        pr[m] = v;
    }
}

extern "C" void kernel_launch(void* const* d_in, const int* in_sizes, int n_in,
                              void* d_out, int out_size) {
    const float* z = (const float*)d_in[0];
    const float* c = (const float*)d_in[1];
    float* qout = (float*)d_out;
    float* pout = (float*)d_out + (size_t)BATCH * K;

    k_zero<<<1, 32>>>();
    k_q<<<BATCH / 512, 256>>>(z, c, qout);
    k_p<<<BATCH / 256, 256>>>(qout, pout);
}